// round 12
// baseline (speedup 1.0000x reference)
#include <cuda_runtime.h>
#include <math.h>

#define HS   14
#define SEQ  197
#define FULL 0xFFFFFFFFu

__global__ __launch_bounds__(32) void blob_loss_kernel(
    const float* __restrict__ dot_qk,
    float* __restrict__ out,
    float inv_n)
{
    // Labels live in padded address space: addr = row*16 + col (<= 221),
    // order-isomorphic to flat index, so min-root identity matches reference.
    // P32: union-find-ish parent/label slots (u32 for atomicMin). 256 slots so
    // index 0xFF (background) is in-bounds and holds 0xFF.
    __shared__ int   P32[256];
    __shared__ float PU[224];

    const int lane = threadIdx.x;
    const int task = blockIdx.x;

    const float* rowp  = dot_qk + (size_t)task * (SEQ * SEQ) + 1;
    const bool   rowok = (lane < HS);
    const float* myrow = rowp + lane * HS;

    #pragma unroll
    for (int i = 0; i < 8; i++) P32[lane * 8 + i] = 0xFF;
    #pragma unroll
    for (int i = lane; i < 224; i += 32) PU[i] = 0.f;

    // ---- lane r owns row r: 14 register-resident floats
    float x[HS];
    float rs = 0.f;
    #pragma unroll
    for (int c = 0; c < HS; c++) {
        x[c] = rowok ? myrow[c] : 0.f;
        rs += x[c];
    }
    float s = rs;
    #pragma unroll
    for (int o = 16; o; o >>= 1) s += __shfl_xor_sync(FULL, s, o);
    const float m = s * (1.0f / 196.0f);

    // ---- mask, xv, B
    unsigned mk = 0;
    float xv[HS];
    float b = 0.f;
    #pragma unroll
    for (int c = 0; c < HS; c++) {
        xv[c] = fmaxf(x[c] - m, 0.f) + 1e-9f;
        if (rowok && x[c] > m) { mk |= (1u << c); b += xv[c]; }
    }
    float B = b;
    #pragma unroll
    for (int o = 16; o; o >>= 1) B += __shfl_xor_sync(FULL, B, o);

    // ---- pack byte labels; seed P32 for masked pixels (after blanket 0xFF init)
    __syncwarp();
    const unsigned abase = lane << 4;
    unsigned w[4], nn[4];
    #pragma unroll
    for (int i = 0; i < 4; i++) {
        unsigned v = 0;
        #pragma unroll
        for (int j = 0; j < 4; j++) {
            int c = 4 * i + j;
            unsigned byte = (c < HS && ((mk >> c) & 1u)) ? (abase + c) : 0xFFu;
            v |= byte << (8 * j);
        }
        w[i]  = v;
        nn[i] = __vcmpeq4(v, FULL);   // 0xFF bytes where background/pad
    }
    if (rowok) {
        #pragma unroll
        for (int c = 0; c < HS; c++)
            if ((mk >> c) & 1u) P32[abase + c] = abase + c;
    }
    __syncwarp();

    // ---- CC: SV-style hook (atomicMin to root slot) + double jump. O(log) iters.
    for (int it = 0; it < 64; it++) {
        // 9-neighborhood byte-min in registers (t[i] <= w[i] bytewise)
        unsigned t[4];
        {
            unsigned sr0 = __funnelshift_r(w[0], w[1], 8);
            unsigned sr1 = __funnelshift_r(w[1], w[2], 8);
            unsigned sr2 = __funnelshift_r(w[2], w[3], 8);
            unsigned sr3 = __funnelshift_r(w[3], FULL, 8);
            unsigned sl0 = __funnelshift_l(FULL, w[0], 8);
            unsigned sl1 = __funnelshift_l(w[0], w[1], 8);
            unsigned sl2 = __funnelshift_l(w[1], w[2], 8);
            unsigned sl3 = __funnelshift_l(w[2], w[3], 8);
            unsigned h0 = __vminu4(w[0], __vminu4(sr0, sl0));
            unsigned h1 = __vminu4(w[1], __vminu4(sr1, sl1));
            unsigned h2 = __vminu4(w[2], __vminu4(sr2, sl2));
            unsigned h3 = __vminu4(w[3], __vminu4(sr3, sl3));
            unsigned u0 = __shfl_up_sync(FULL, h0, 1), d0 = __shfl_down_sync(FULL, h0, 1);
            unsigned u1 = __shfl_up_sync(FULL, h1, 1), d1 = __shfl_down_sync(FULL, h1, 1);
            unsigned u2 = __shfl_up_sync(FULL, h2, 1), d2 = __shfl_down_sync(FULL, h2, 1);
            unsigned u3 = __shfl_up_sync(FULL, h3, 1), d3 = __shfl_down_sync(FULL, h3, 1);
            t[0] = __vminu4(h0, __vminu4(u0, d0)) | nn[0];
            t[1] = __vminu4(h1, __vminu4(u1, d1)) | nn[1];
            t[2] = __vminu4(h2, __vminu4(u2, d2)) | nn[2];
            t[3] = __vminu4(h3, __vminu4(u3, d3)) | nn[3];
        }

        // hook: offer improved candidate directly to current root slot
        if (rowok) {
            #pragma unroll
            for (int c = 0; c < HS; c++) {
                if ((mk >> c) & 1u) {
                    const int i = c >> 2, sh = (c & 3) * 8;
                    unsigned tb = (t[i] >> sh) & 0xFFu;
                    unsigned wb = (w[i] >> sh) & 0xFFu;
                    if (tb < wb) atomicMin(&P32[wb], (int)tb);
                }
            }
        }
        __syncwarp();

        // jump: w = P[P[t]] (values are masked addresses; slots always valid)
        unsigned nw[4] = { nn[0], nn[1], nn[2], nn[3] };
        if (rowok) {
            #pragma unroll
            for (int c = 0; c < HS; c++) {
                if ((mk >> c) & 1u) {
                    const int i = c >> 2, sh = (c & 3) * 8;
                    unsigned tb = (t[i] >> sh) & 0xFFu;
                    unsigned g  = (unsigned)P32[(unsigned)P32[tb]];
                    nw[i] |= g << sh;
                }
            }
        } else {
            nw[0] = nw[1] = nw[2] = nw[3] = FULL;
        }

        unsigned ch = (nw[0] ^ w[0]) | (nw[1] ^ w[1]) | (nw[2] ^ w[2]) | (nw[3] ^ w[3]);
        w[0] = nw[0]; w[1] = nw[1]; w[2] = nw[2]; w[3] = nw[3];
        if (!__any_sync(FULL, ch != 0u)) break;   // also syncs gathers vs next hooks
    }

    // ---- per-component sums (labels are padded addresses)
    __syncwarp();
    if (rowok) {
        #pragma unroll
        for (int c = 0; c < HS; c++) {
            if ((mk >> c) & 1u) {
                const int i = c >> 2, sh = (c & 3) * 8;
                unsigned lb = (w[i] >> sh) & 0xFFu;
                atomicAdd(&PU[lb], xv[c]);
            }
        }
    }
    __syncwarp();

    // ---- entropy at roots (label == own padded address)
    float h = 0.f;
    const float invB = 1.0f / B;
    if (rowok) {
        #pragma unroll
        for (int c = 0; c < HS; c++) {
            if ((mk >> c) & 1u) {
                const int i = c >> 2, sh = (c & 3) * 8;
                unsigned lb = (w[i] >> sh) & 0xFFu;
                if (lb == abase + c) {
                    float pn = PU[lb] * invB;
                    h -= pn * __logf(pn);
                }
            }
        }
    }
    #pragma unroll
    for (int o = 16; o; o >>= 1) h += __shfl_xor_sync(FULL, h, o);
    if (lane == 0) atomicAdd(out, h * inv_n);
}

extern "C" void kernel_launch(void* const* d_in, const int* in_sizes, int n_in,
                              void* d_out, int out_size)
{
    const float* dq = (const float*)d_in[0];
    float* out = (float*)d_out;
    const int n = in_sizes[0] / (SEQ * SEQ);   // 128*12 = 1536

    cudaMemsetAsync(out, 0, sizeof(float));
    blob_loss_kernel<<<n, 32>>>(dq, out, 1.0f / (float)n);
}

// round 13
// speedup vs baseline: 1.7480x; 1.7480x over previous
#include <cuda_runtime.h>
#include <math.h>

#define HS   14
#define SEQ  197
#define FULL 0xFFFFFFFFu

// Two tasks per warp: task A = lanes 0-15, task B = lanes 16-31.
// sub-lane (lane&15) 0..13 owns a grid row; sub 14,15 are all-0xFF padding
// (neutral for byte-min and the natural top/bottom border between halves).
__global__ __launch_bounds__(32) void blob_loss_kernel(
    const float* __restrict__ dot_qk,
    float* __restrict__ out,
    float inv_n)
{
    // per-task byte label mirrors (256 each; slot 255 stays 0xFF for background)
    __shared__ unsigned char SLAB[2][512];
    __shared__ float PU[2][224];

    const int lane = threadIdx.x;
    const int sub  = lane & 15;
    const int half = lane >> 4;                 // 0 = task A, 1 = task B
    const int task = blockIdx.x * 2 + half;
    const unsigned tofs = (unsigned)(half << 8);  // 0 or 256 into SLAB

    const bool   rowok = (sub < HS);
    const float* myrow = dot_qk + (size_t)task * (SEQ * SEQ) + 1 + sub * HS;

    // init: SLAB both buffers to 0xFF (512B / 32 lanes = 16B each), PU to 0
    ((uint4*)SLAB[0])[lane] = make_uint4(FULL, FULL, FULL, FULL);
    ((uint4*)SLAB[1])[lane] = make_uint4(FULL, FULL, FULL, FULL);
    #pragma unroll
    for (int i = lane; i < 448; i += 32) PU[0][i] = 0.f;   // PU is contiguous [2][224]

    // ---- load 14 register floats per row-lane
    float x[HS];
    float rs = 0.f;
    #pragma unroll
    for (int c = 0; c < HS; c++) {
        x[c] = rowok ? myrow[c] : 0.f;
        rs += x[c];
    }
    // mean within each 16-lane half
    float s = rs;
    #pragma unroll
    for (int o = 8; o; o >>= 1) s += __shfl_xor_sync(FULL, s, o);
    const float m = s * (1.0f / 196.0f);

    // ---- mask, xv, B (per half)
    unsigned mk = 0;
    float xv[HS];
    float b = 0.f;
    #pragma unroll
    for (int c = 0; c < HS; c++) {
        xv[c] = fmaxf(x[c] - m, 0.f) + 1e-9f;
        if (rowok && x[c] > m) { mk |= (1u << c); b += xv[c]; }
    }
    float B = b;
    #pragma unroll
    for (int o = 8; o; o >>= 1) B += __shfl_xor_sync(FULL, B, o);

    // ---- pack initial byte labels, task-local padded addresses (row*16+col <= 221)
    const unsigned abase = (unsigned)(sub << 4);
    unsigned w0, w1, w2, w3;
    {
        unsigned ww[4];
        #pragma unroll
        for (int i = 0; i < 4; i++) {
            unsigned v = 0;
            #pragma unroll
            for (int j = 0; j < 4; j++) {
                int c = 4 * i + j;
                unsigned byte = (c < HS && ((mk >> c) & 1u)) ? (abase + c) : 0xFFu;
                v |= byte << (8 * j);
            }
            ww[i] = v;
        }
        w0 = ww[0]; w1 = ww[1]; w2 = ww[2]; w3 = ww[3];
    }
    const unsigned n0 = __vcmpeq4(w0, FULL);
    const unsigned n1 = __vcmpeq4(w1, FULL);
    const unsigned n2 = __vcmpeq4(w2, FULL);
    const unsigned n3 = __vcmpeq4(w3, FULL);

    // ---- CC: register 8-neighbor byte-min + shared pointer jump.
    //      Fully branch-free across all 32 lanes; cap 196 (sound upper bound).
    int bi = 0;
    for (int it = 0; it < 196; it++) {
        unsigned sr0 = __funnelshift_r(w0, w1, 8);
        unsigned sr1 = __funnelshift_r(w1, w2, 8);
        unsigned sr2 = __funnelshift_r(w2, w3, 8);
        unsigned sr3 = __funnelshift_r(w3, FULL, 8);
        unsigned sl0 = __funnelshift_l(FULL, w0, 8);
        unsigned sl1 = __funnelshift_l(w0, w1, 8);
        unsigned sl2 = __funnelshift_l(w1, w2, 8);
        unsigned sl3 = __funnelshift_l(w2, w3, 8);
        unsigned h0 = __vminu4(w0, __vminu4(sr0, sl0));
        unsigned h1 = __vminu4(w1, __vminu4(sr1, sl1));
        unsigned h2 = __vminu4(w2, __vminu4(sr2, sl2));
        unsigned h3 = __vminu4(w3, __vminu4(sr3, sl3));
        // vertical: half boundaries guarded by all-0xFF pad lanes (14,15,30,31);
        // lane 0 shfl_up returns own h (harmless for min)
        unsigned u0 = __shfl_up_sync(FULL, h0, 1), d0 = __shfl_down_sync(FULL, h0, 1);
        unsigned u1 = __shfl_up_sync(FULL, h1, 1), d1 = __shfl_down_sync(FULL, h1, 1);
        unsigned u2 = __shfl_up_sync(FULL, h2, 1), d2 = __shfl_down_sync(FULL, h2, 1);
        unsigned u3 = __shfl_up_sync(FULL, h3, 1), d3 = __shfl_down_sync(FULL, h3, 1);
        unsigned t0 = __vminu4(h0, __vminu4(u0, d0)) | n0;
        unsigned t1 = __vminu4(h1, __vminu4(u1, d1)) | n1;
        unsigned t2 = __vminu4(h2, __vminu4(u2, d2)) | n2;
        unsigned t3 = __vminu4(h3, __vminu4(u3, d3)) | n3;

        // mirror row (pad lanes write 0xFF to slots 224..255 — harmless, keeps 0xFF)
        *(uint4*)&SLAB[bi][tofs + abase] = make_uint4(t0, t1, t2, t3);
        __syncwarp();

        // pointer jump: lab = S[lab]; background bytes (0xFF) hit S[255] = 0xFF
        const unsigned char* S = &SLAB[bi][tofs];
        unsigned b0  = S[t0 & 0xFFu],         c1  = S[(t0 >> 8) & 0xFFu];
        unsigned c2  = S[(t0 >> 16) & 0xFFu], c3  = S[t0 >> 24];
        unsigned c4  = S[t1 & 0xFFu],         c5  = S[(t1 >> 8) & 0xFFu];
        unsigned c6  = S[(t1 >> 16) & 0xFFu], c7  = S[t1 >> 24];
        unsigned c8  = S[t2 & 0xFFu],         c9  = S[(t2 >> 8) & 0xFFu];
        unsigned c10 = S[(t2 >> 16) & 0xFFu], c11 = S[t2 >> 24];
        unsigned c12 = S[t3 & 0xFFu],         c13 = S[(t3 >> 8) & 0xFFu];
        unsigned g0 = b0  | (c1  << 8) | (c2  << 16) | (c3  << 24);
        unsigned g1 = c4  | (c5  << 8) | (c6  << 16) | (c7  << 24);
        unsigned g2 = c8  | (c9  << 8) | (c10 << 16) | (c11 << 24);
        unsigned g3 = c12 | (c13 << 8) | 0xFFFF0000u;

        unsigned ch = (g0 ^ w0) | (g1 ^ w1) | (g2 ^ w2) | (g3 ^ w3);
        w0 = g0; w1 = g1; w2 = g2; w3 = g3;
        bi ^= 1;
        if (!__any_sync(FULL, ch != 0u)) break;
    }

    // ---- per-component sums (task-local padded addresses)
    __syncwarp();
    float* PUt = PU[half];
    if (rowok) {
        #pragma unroll
        for (int c = 0; c < HS; c++) {
            if ((mk >> c) & 1u) {
                unsigned lb;
                if      (c < 4)  lb = (w0 >> (8 * c))        & 0xFFu;
                else if (c < 8)  lb = (w1 >> (8 * (c - 4)))  & 0xFFu;
                else if (c < 12) lb = (w2 >> (8 * (c - 8)))  & 0xFFu;
                else             lb = (w3 >> (8 * (c - 12))) & 0xFFu;
                atomicAdd(&PUt[lb], xv[c]);
            }
        }
    }
    __syncwarp();

    // ---- entropy at roots (label == own padded address), reduce per half
    float h = 0.f;
    const float invB = 1.0f / B;
    if (rowok) {
        #pragma unroll
        for (int c = 0; c < HS; c++) {
            if ((mk >> c) & 1u) {
                unsigned lb;
                if      (c < 4)  lb = (w0 >> (8 * c))        & 0xFFu;
                else if (c < 8)  lb = (w1 >> (8 * (c - 4)))  & 0xFFu;
                else if (c < 12) lb = (w2 >> (8 * (c - 8)))  & 0xFFu;
                else             lb = (w3 >> (8 * (c - 12))) & 0xFFu;
                if (lb == abase + c) {
                    float pn = PUt[lb] * invB;
                    h -= pn * __logf(pn);
                }
            }
        }
    }
    #pragma unroll
    for (int o = 8; o; o >>= 1) h += __shfl_xor_sync(FULL, h, o);
    if (sub == 0) atomicAdd(out, h * inv_n);
}

extern "C" void kernel_launch(void* const* d_in, const int* in_sizes, int n_in,
                              void* d_out, int out_size)
{
    const float* dq = (const float*)d_in[0];
    float* out = (float*)d_out;
    const int n = in_sizes[0] / (SEQ * SEQ);   // 128*12 = 1536 (even)

    cudaMemsetAsync(out, 0, sizeof(float));
    blob_loss_kernel<<<n / 2, 32>>>(dq, out, 1.0f / (float)n);
}